// round 6
// baseline (speedup 1.0000x reference)
#include <cuda_runtime.h>
#include <math.h>

#define BATCH 8
#define CINC 64
#define COUTC 64
#define HDIM 128
#define WDIM 128
#define NPIX (HDIM*WDIM)          // 16384
#define NHEADS 4
#define CRED 32
#define TOT (BATCH*NPIX)          // 131072
#define KDIM (NHEADS*CRED)        // 128

typedef unsigned long long u64;

// packed fp32x2 helpers (Blackwell FFMA2 — only reachable via PTX)
#define FMA2(acc, a, b) \
    asm("fma.rn.f32x2 %0, %1, %2, %0;" : "+l"(acc) : "l"(a), "l"(b))
#define PACK_DUP(dst, f) \
    asm("mov.b64 %0, {%1, %1};" : "=l"(dst) : "r"(__float_as_uint(f)))
#define PACK2(dst, lo, hi) \
    asm("mov.b64 %0, {%1, %2};" : "=l"(dst) : "r"(__float_as_uint(lo)), "r"(__float_as_uint(hi)))
#define UNPACK2(lo, hi, src) \
    asm("mov.b64 {%0, %1}, %2;" : "=r"(lo), "=r"(hi) : "l"(src))

// -------- device scratch (no allocation allowed in kernel_launch) --------
__device__ float g_xr[(size_t)TOT*CRED];            // [B*N][32] node-major
__device__ float g_as[(size_t)TOT*NHEADS];
__device__ float g_ad[(size_t)TOT*NHEADS];
__device__ float g_out[(size_t)TOT*COUTC];          // [B][64][N] channel-major
__device__ float g_M[COUTC*KDIM];                   // [o][k] row-major
__device__ float g_pq[2*NHEADS*CRED];               // p (128) then q (128)
__device__ float g_wrb[COUTC];
__device__ float g_chsum[COUTC];
__device__ float g_chsq[COUTC];

// ---------------- P: fold w_restore/w_lin/att into M, p, q, wrb ----------
__global__ void __launch_bounds__(256) kP(const float* __restrict__ w_lin,
                   const float* __restrict__ att_src,
                   const float* __restrict__ att_dst,
                   const float* __restrict__ b_gat,
                   const float* __restrict__ w_restore) {
    __shared__ float wl[KDIM*CRED];     // w_lin  [h*32+cr][c]  (16 KB)
    __shared__ float wrs[COUTC*CRED];   // w_restore [o][cr]    (8 KB)
    int t = threadIdx.x;
    for (int f = t; f < KDIM*CRED;  f += 256) wl[f]  = w_lin[f];
    for (int f = t; f < COUTC*CRED; f += 256) wrs[f] = w_restore[f];
    __syncthreads();

    for (int idx = t; idx < COUTC*KDIM; idx += 256) {
        int o = idx >> 7, k = idx & 127, h = k >> 5, c = k & 31;
        float s = 0.f;
        #pragma unroll 8
        for (int cr = 0; cr < CRED; cr++)
            s += wrs[o*CRED+cr] * wl[(h*CRED+cr)*CRED + c];
        g_M[idx] = 0.25f * s;             // head-mean folded in
    }
    {   // p / q vectors: p_h = W_h^T att_src[h]  (a_s[v,h] = p_h . xr[v])
        int which = t >> 7;               // 0 -> p (att_src), 1 -> q (att_dst)
        int hc = t & 127;
        int h = hc >> 5, c = hc & 31;
        const float* att = which ? att_dst : att_src;
        float s = 0.f;
        #pragma unroll 8
        for (int cr = 0; cr < CRED; cr++)
            s += att[h*CRED+cr] * wl[(h*CRED+cr)*CRED + c];
        g_pq[t] = s;
    }
    if (t < COUTC) {
        float s = 0.f;
        #pragma unroll 8
        for (int c = 0; c < CRED; c++) s += wrs[t*CRED+c] * b_gat[c];
        g_wrb[t] = s;
        g_chsum[t] = 0.f;                 // zero BN accumulators for this run
        g_chsq[t]  = 0.f;
    }
}

// ------------- A: xr = w_reduce @ x  (node-major) + attention logits -----
// Packed-pair weights: wrp[c2][cin] = (w_reduce[2c2][cin], w_reduce[2c2+1][cin])
__global__ void __launch_bounds__(256) kA(const float* __restrict__ x,
                                          const float* __restrict__ w_reduce) {
    __shared__ u64   wrp[(CRED/2)*CINC];  // 16x64 pairs (8 KB)
    __shared__ float pq[2*NHEADS*CRED];
    int t = threadIdx.x;
    for (int f = t; f < (CRED/2)*CINC; f += 256) {
        int c2 = f >> 6, cin = f & 63;
        u64 p;
        PACK2(p, w_reduce[(2*c2)*CINC + cin], w_reduce[(2*c2+1)*CINC + cin]);
        wrp[f] = p;
    }
    pq[t] = g_pq[t];
    __syncthreads();

    int gid = blockIdx.x * 256 + t;       // 0..TOT-1
    int b = gid >> 14;
    int pix = gid & (NPIX-1);
    const float* xb = x + ((size_t)b*CINC)*NPIX + pix;

    u64 acc2[CRED/2];
    #pragma unroll
    for (int c2 = 0; c2 < CRED/2; c2++) acc2[c2] = 0ull;

    #pragma unroll 4
    for (int cin = 0; cin < CINC; cin++) {
        float xv = xb[(size_t)cin*NPIX];
        u64 xp; PACK_DUP(xp, xv);
        #pragma unroll
        for (int c2 = 0; c2 < CRED/2; c2++)
            FMA2(acc2[c2], wrp[c2*CINC + cin], xp);
    }

    float acc[CRED];
    #pragma unroll
    for (int c2 = 0; c2 < CRED/2; c2++) {
        unsigned lo, hi; UNPACK2(lo, hi, acc2[c2]);
        acc[2*c2]   = __uint_as_float(lo);    // low lane = even channel
        acc[2*c2+1] = __uint_as_float(hi);
    }

    float4* xro = (float4*)&g_xr[(size_t)gid*CRED];
    #pragma unroll
    for (int c4 = 0; c4 < CRED/4; c4++)
        xro[c4] = make_float4(acc[4*c4], acc[4*c4+1], acc[4*c4+2], acc[4*c4+3]);

    float asv[NHEADS], adv[NHEADS];
    #pragma unroll
    for (int h = 0; h < NHEADS; h++) {
        float ps = 0.f, qs = 0.f;
        #pragma unroll
        for (int c = 0; c < CRED; c++) {
            ps += pq[h*CRED+c]       * acc[c];
            qs += pq[128 + h*CRED+c] * acc[c];
        }
        asv[h] = ps; adv[h] = qs;
    }
    *(float4*)&g_as[(size_t)gid*NHEADS] = make_float4(asv[0],asv[1],asv[2],asv[3]);
    *(float4*)&g_ad[(size_t)gid*NHEADS] = make_float4(adv[0],adv[1],adv[2],adv[3]);
}

// ====== B12: fused GAT aggregation + restore GEMM + residual + BN-stats ==
// One block per (batch, grid-row): 128 pixels. 4-neighborhood of a grid row
// lives in rows i-1, i, i+1. xr neighbor rows are read DIRECTLY from global
// (warp-coalesced 128B rows, L2-resident) so smem fits 2 CTAs/SM and phases
// of co-resident CTAs overlap.
//
// Dynamic smem layout (floats):
//   Ms  [128][68]   @ 0       (8704)   M transposed: [k][o], padded rows
//   Ss  [128][132]  @ 8704    (16896)  S: [k][p], padded rows
//   As3 [3][128][4] @ 25600   (1536)   a_src rows i-1,i,i+1
//   Ad4 [128][4]    @ 27136   (512)    a_dst row i
//   wrb [64]        @ 27648   (64)
// total 27712 floats = 110848 B  (x2 = 221.7 KB <= 228 KB/SM)
#define SM_MS   0
#define SM_SS   8704
#define SM_AS   25600
#define SM_AD   27136
#define SM_WRB  27648
#define SM_FLOATS 27712

__global__ void __launch_bounds__(256, 2) kB12(const float* __restrict__ x) {
    extern __shared__ float sm[];
    float* Ms  = sm + SM_MS;
    float* Ss  = sm + SM_SS;
    float* As3 = sm + SM_AS;
    float* Ad4 = sm + SM_AD;
    float* wrbs= sm + SM_WRB;

    int t = threadIdx.x;
    int b = blockIdx.x >> 7;
    int i = blockIdx.x & 127;             // grid row
    int gbase = b << 14;

    // ---- stage M (transposed) and wrb ----
    for (int f = t; f < COUTC*KDIM; f += 256)
        Ms[(f & 127)*68 + (f >> 7)] = g_M[f];
    if (t < COUTC) wrbs[t] = g_wrb[t];

    // ---- stage a_src rows i-1,i,i+1 and a_dst row i ----
    for (int f = t; f < 3*128; f += 256) {
        int r = f >> 7, j = f & 127;
        int gi = i - 1 + r;
        float4 v = make_float4(0.f,0.f,0.f,0.f);
        if (gi >= 0 && gi < HDIM)
            v = *(const float4*)&g_as[((size_t)(gbase + gi*WDIM + j))*NHEADS];
        *(float4*)&As3[(r*128 + j)*4] = v;
    }
    if (t < 128)
        *(float4*)&Ad4[t*4] = *(const float4*)&g_ad[((size_t)(gbase + i*WDIM + t))*NHEADS];
    __syncthreads();

    // ---- phase 2: softmax + weighted neighbor sums -> Ss[k][p] ----
    // xr rows read straight from g_xr: per (j,u) a coalesced 128B warp load.
    // j blocked by 4: one STS.128 per head per j-block, conflict-free.
    {
        int w = t >> 5, lane = t & 31;
        bool up = (i > 0), dn = (i < HDIM-1);
        for (int jb = 0; jb < 4; jb++) {
            float sjh[NHEADS][4];
            #pragma unroll
            for (int jq = 0; jq < 4; jq++) {
                int j = w*16 + jb*4 + jq;
                bool lf = (j > 0), rt = (j < WDIM-1);
                // u: 0=self(r1,j) 1=up(r0,j) 2=down(r2,j) 3=left 4=right
                int  ru[5] = {1, 0, 2, 1, 1};
                int  ju[5] = {j, j, j, (j>0? j-1 : j), (j<WDIM-1? j+1 : j)};
                bool vl[5] = {true, up, dn, lf, rt};

                // kick off the 5 xr loads early (independent, L2-latency hidden)
                float xv[5];
                #pragma unroll
                for (int u = 0; u < 5; u++) {
                    int gi = i - 1 + ru[u];
                    xv[u] = vl[u]
                        ? g_xr[((size_t)(gbase + gi*WDIM + ju[u]))*CRED + lane]
                        : 0.f;
                }

                float ex[5][NHEADS], den[NHEADS];
                #pragma unroll
                for (int h = 0; h < NHEADS; h++) {
                    float adh = Ad4[j*4 + h];
                    float e[5]; float mx = -1e30f;
                    #pragma unroll
                    for (int u = 0; u < 5; u++) {
                        float ev = As3[(ru[u]*128 + ju[u])*4 + h] + adh;
                        ev = ev > 0.f ? ev : 0.2f*ev;   // leaky_relu(0.2)
                        e[u] = ev;
                        if (vl[u]) mx = fmaxf(mx, ev);
                    }
                    float d = 0.f;
                    #pragma unroll
                    for (int u = 0; u < 5; u++) {
                        float xx = vl[u] ? __expf(e[u]-mx) : 0.f;
                        ex[u][h] = xx; d += xx;
                    }
                    den[h] = 1.f / d;
                }
                #pragma unroll
                for (int h = 0; h < NHEADS; h++) {
                    float s = 0.f;
                    #pragma unroll
                    for (int u = 0; u < 5; u++) s += ex[u][h] * xv[u];
                    sjh[h][jq] = s * den[h];
                }
            }
            int j0 = w*16 + jb*4;
            #pragma unroll
            for (int h = 0; h < NHEADS; h++)
                *(float4*)&Ss[(h*CRED + lane)*132 + j0] =
                    make_float4(sjh[h][0], sjh[h][1], sjh[h][2], sjh[h][3]);
        }
    }
    __syncthreads();

    // ---- phase 3: GEMM via packed FFMA2. Lanes = adjacent output channels:
    //      acc2[op][ip] = (out[o0+2op], out[o0+2op+1]) at pixel p0+ip.
    //      M pairs come packed straight from smem (consecutive o).
    int po = t & 31, oo = t >> 5;
    int p0 = po*4, o0 = oo*8;
    u64 acc2[4][4];
    #pragma unroll
    for (int a0 = 0; a0 < 4; a0++)
        #pragma unroll
        for (int a1 = 0; a1 < 4; a1++) acc2[a0][a1] = 0ull;

    #pragma unroll 1
    for (int k0 = 0; k0 < KDIM; k0 += 8) {
        #pragma unroll
        for (int kk = 0; kk < 8; kk++) {
            int k = k0 + kk;
            const ulonglong2* mr = (const ulonglong2*)&Ms[k*68 + o0]; // 16B aligned
            ulonglong2 ma = mr[0], mb = mr[1];
            u64 mp[4] = {ma.x, ma.y, mb.x, mb.y};
            float4 sv = *(const float4*)&Ss[k*132 + p0];
            u64 sp[4];
            PACK_DUP(sp[0], sv.x); PACK_DUP(sp[1], sv.y);
            PACK_DUP(sp[2], sv.z); PACK_DUP(sp[3], sv.w);
            #pragma unroll
            for (int op = 0; op < 4; op++)
                #pragma unroll
                for (int ip = 0; ip < 4; ip++)
                    FMA2(acc2[op][ip], mp[op], sp[ip]);
        }
    }

    // unpack to scalar tile [8 o][4 p]
    float acc[8][4];
    #pragma unroll
    for (int op = 0; op < 4; op++)
        #pragma unroll
        for (int ip = 0; ip < 4; ip++) {
            unsigned lo, hi; UNPACK2(lo, hi, acc2[op][ip]);
            acc[2*op][ip]   = __uint_as_float(lo);   // low lane = even o offset
            acc[2*op+1][ip] = __uint_as_float(hi);
        }

    // ---- epilogue: +wrb +residual, store, per-channel BN partial sums ----
    float csum[8], csq[8];
    #pragma unroll
    for (int io = 0; io < 8; io++) {
        int o = o0 + io;
        size_t off = (((size_t)b*COUTC + o) << 14) + i*WDIM + p0;
        float4 xv = *(const float4*)&x[off];
        float wb = wrbs[o];
        float4 r;
        r.x = acc[io][0] + wb + xv.x;
        r.y = acc[io][1] + wb + xv.y;
        r.z = acc[io][2] + wb + xv.z;
        r.w = acc[io][3] + wb + xv.w;
        *(float4*)&g_out[off] = r;
        csum[io] = r.x + r.y + r.z + r.w;
        csq[io]  = r.x*r.x + r.y*r.y + r.z*r.z + r.w*r.w;
    }
    // warp owns channels o0..o0+7 exclusively over all 128 pixels of this row
    #pragma unroll
    for (int io = 0; io < 8; io++) {
        #pragma unroll
        for (int off = 16; off > 0; off >>= 1) {
            csum[io] += __shfl_down_sync(0xffffffffu, csum[io], off);
            csq[io]  += __shfl_down_sync(0xffffffffu, csq[io],  off);
        }
    }
    if (po == 0) {
        #pragma unroll
        for (int io = 0; io < 8; io++) {
            atomicAdd(&g_chsum[o0+io], csum[io]);
            atomicAdd(&g_chsq[o0+io],  csq[io]);
        }
    }
}

// ------------------ D: normalize + affine + relu -------------------------
__global__ void __launch_bounds__(256) kD(const float* __restrict__ gamma,
                                          const float* __restrict__ beta,
                                          float* __restrict__ out) {
    size_t e4 = (size_t)blockIdx.x * 256 + threadIdx.x;   // float4 index
    size_t e = e4 * 4;
    int c = (int)((e >> 14) & 63);
    const float invcnt = 1.f / (float)(BATCH*NPIX);
    float mean = g_chsum[c] * invcnt;
    float var  = g_chsq[c] * invcnt - mean*mean;
    float inv  = rsqrtf(var + 1e-5f) * gamma[c];
    float sh   = beta[c] - mean * inv;
    float4 v = *(const float4*)&g_out[e];
    float4 r;
    r.x = fmaxf(v.x*inv + sh, 0.f);
    r.y = fmaxf(v.y*inv + sh, 0.f);
    r.z = fmaxf(v.z*inv + sh, 0.f);
    r.w = fmaxf(v.w*inv + sh, 0.f);
    *(float4*)&out[e] = r;
}

// -------------------------------------------------------------------------
extern "C" void kernel_launch(void* const* d_in, const int* in_sizes, int n_in,
                              void* d_out, int out_size) {
    const float* x         = (const float*)d_in[0];
    const float* w_reduce  = (const float*)d_in[1];
    const float* w_lin     = (const float*)d_in[2];
    const float* att_src   = (const float*)d_in[3];
    const float* att_dst   = (const float*)d_in[4];
    const float* b_gat     = (const float*)d_in[5];
    const float* w_restore = (const float*)d_in[6];
    const float* bn_gamma  = (const float*)d_in[7];
    const float* bn_beta   = (const float*)d_in[8];
    // d_in[9]=src, d_in[10]=dst : fixed 4-neighbor grid + self loops (implicit)
    float* out = (float*)d_out;

    // Idempotent, deterministic, not stream-ordered: safe under graph capture,
    // no static guards (harness forbids call-count-dependent behavior).
    cudaFuncSetAttribute(kB12, cudaFuncAttributeMaxDynamicSharedMemorySize,
                         SM_FLOATS * (int)sizeof(float));

    kP<<<1, 256>>>(w_lin, att_src, att_dst, b_gat, w_restore);
    kA<<<TOT/256, 256>>>(x, w_reduce);
    kB12<<<TOT/WDIM, 256, SM_FLOATS*sizeof(float)>>>(x);
    kD<<<(size_t)(TOT)*COUTC/(256*4), 256>>>(bn_gamma, bn_beta, out);
}